// round 4
// baseline (speedup 1.0000x reference)
#include <cuda_runtime.h>
#include <math.h>

#define BB 8
#define TT 2048
#define HH 1024
#define G3 3072
#define NCTA 128
#define NTHR 128
#define FPAD 32      // one flag per 128B line
#define SHSTR 1032   // padded h row stride (floats); 1032 % 32 == 8 -> optimal 2-phase LDS.64

typedef unsigned long long u64;

// ---------------- persistent scratch (device globals; zero-initialized) -----
__device__ float g_xproj[(size_t)TT * BB * G3];   // [t][b][3H]
__device__ float g_h[2][BB * HH];                 // double-buffered hidden state
__device__ unsigned int g_flags[NCTA * FPAD];     // grid-barrier flags (monotonic)

__device__ __forceinline__ void st_release_gpu(unsigned int* p, unsigned int v) {
    asm volatile("st.release.gpu.u32 [%0], %1;" :: "l"(p), "r"(v) : "memory");
}
__device__ __forceinline__ unsigned int ld_acquire_gpu(const unsigned int* p) {
    unsigned int v;
    asm volatile("ld.acquire.gpu.u32 %0, [%1];" : "=r"(v) : "l"(p) : "memory");
    return v;
}
// packed fp32x2 FMA (Blackwell): d = a*b + c elementwise on (lo,hi)
__device__ __forceinline__ u64 fma2(u64 a, u64 b, u64 c) {
    u64 d;
    asm("fma.rn.f32x2 %0, %1, %2, %3;" : "=l"(d) : "l"(a), "l"(b), "l"(c));
    return d;
}
__device__ __forceinline__ float fold2(u64 v) {
    return __uint_as_float((unsigned)v) + __uint_as_float((unsigned)(v >> 32));
}
__device__ __forceinline__ float sigmoidf_(float v) {
    return 1.0f / (1.0f + expf(-v));
}

// ---------------- kernel A: x_proj = x @ W_ih^T + b_ih ----------------------
// M=16384, N=3072, K=1024. Tile 64(M) x 128(N) x 16(K); microtile 4x8.
// Microtile cols = tx + 16u  ->  Bs LDS addresses tx*9 mod 16 bijective:
// conflict-free (1-phase) shared loads. Output written [t][b][3H].
#define BM 64
#define BN 128
#define BKK 16
#define APAD 18
#define BPAD 18

__global__ void __launch_bounds__(256, 2) xproj_gemm_kernel(
    const float* __restrict__ x,     // [B*T, H] == [b][t][h]
    const float* __restrict__ Wih,   // [3H, H]
    const float* __restrict__ bih)   // [3H]
{
    __shared__ float As[BM * APAD];   // [64][18]  (k contiguous)
    __shared__ float Bs[BN * BPAD];   // [128][18]

    const int tid = threadIdx.x;
    const int m0 = blockIdx.y * BM;
    const int n0 = blockIdx.x * BN;
    const int tx = tid & 15;          // N dir: cols tx + 16u, u<8
    const int ty = tid >> 4;          // M dir: rows ty*4 .. ty*4+3

    const int ldRow = tid >> 2;       // 0..63
    const int ldCol = (tid & 3) * 4;  // 0,4,8,12

    const float* aPtr  = x   + (size_t)(m0 + ldRow) * HH + ldCol;
    const float* bPtr0 = Wih + (size_t)(n0 + ldRow) * HH + ldCol;
    const float* bPtr1 = Wih + (size_t)(n0 + ldRow + 64) * HH + ldCol;

    u64 acc[4][8];
#pragma unroll
    for (int i = 0; i < 4; ++i)
#pragma unroll
        for (int u = 0; u < 8; ++u) acc[i][u] = 0ull;

    for (int k0 = 0; k0 < HH; k0 += BKK) {
        float4 av  = *(const float4*)(aPtr  + k0);
        float4 bv0 = *(const float4*)(bPtr0 + k0);
        float4 bv1 = *(const float4*)(bPtr1 + k0);

        *(float2*)&As[ldRow * APAD + ldCol + 0] = make_float2(av.x, av.y);
        *(float2*)&As[ldRow * APAD + ldCol + 2] = make_float2(av.z, av.w);
        *(float2*)&Bs[ldRow * BPAD + ldCol + 0] = make_float2(bv0.x, bv0.y);
        *(float2*)&Bs[ldRow * BPAD + ldCol + 2] = make_float2(bv0.z, bv0.w);
        *(float2*)&Bs[(ldRow + 64) * BPAD + ldCol + 0] = make_float2(bv1.x, bv1.y);
        *(float2*)&Bs[(ldRow + 64) * BPAD + ldCol + 2] = make_float2(bv1.z, bv1.w);
        __syncthreads();

#pragma unroll
        for (int kk2 = 0; kk2 < BKK / 2; ++kk2) {
            u64 a2[4];
#pragma unroll
            for (int i = 0; i < 4; ++i)
                a2[i] = *(const u64*)&As[(ty * 4 + i) * APAD + kk2 * 2];
            u64 b2[8];
#pragma unroll
            for (int u = 0; u < 8; ++u)
                b2[u] = *(const u64*)&Bs[(tx + 16 * u) * BPAD + kk2 * 2];
#pragma unroll
            for (int i = 0; i < 4; ++i)
#pragma unroll
                for (int u = 0; u < 8; ++u)
                    acc[i][u] = fma2(a2[i], b2[u], acc[i][u]);
        }
        __syncthreads();
    }

    // Epilogue: scatter to [t][b][3H]
#pragma unroll
    for (int i = 0; i < 4; ++i) {
        int m = m0 + ty * 4 + i;
        int b = m >> 11;          // m / 2048
        int t = m & 2047;
        float* orow = g_xproj + ((size_t)t * BB + b) * G3 + n0;
#pragma unroll
        for (int u = 0; u < 8; ++u) {
            int c = tx + 16 * u;
            orow[c] = fold2(acc[i][u]) + __ldg(bih + n0 + c);
        }
    }
}

// ---------------- kernel B: persistent recurrence ---------------------------
// 128 CTAs x 128 threads (4 warps). Warp w owns 2 hidden cols c0 = cta*8+2w,
// c1 = c0+1; their 6 W_hh rows stay in SMEM. Lane = (b = lane&7, ks = lane>>3):
// lane accumulates all 6 (gate,col) partials for ONE batch over k2 % 4 == ks.
// W loads broadcast 8-way (4 distinct addrs); h loads 2-phase via SHSTR pad.
__global__ void __launch_bounds__(NTHR, 1) gru_recurrent_kernel(
    const float* __restrict__ Whh,   // [3H, H]
    const float* __restrict__ bhh,   // [3H]
    float* __restrict__ out)         // [B, T, H]
{
    extern __shared__ float smem[];
    float* sW = smem;                 // [24][1024]
    float* sh = smem + 24 * HH;       // [8][SHSTR]

    const int tid  = threadIdx.x;
    const int cta  = blockIdx.x;
    const int warp = tid >> 5;
    const int lane = tid & 31;
    const int j0   = warp * 2;        // local col pair
    const int c0   = cta * 8 + j0;
    const int c1   = c0 + 1;

    // Load W_hh slice: local row r = j*3 + g  <->  global row g*H + (8*cta + j)
    for (int idx = tid; idx < 24 * (HH / 4); idx += NTHR) {
        int r  = idx / (HH / 4);
        int k4 = idx % (HH / 4);
        int j = r / 3, g = r % 3;
        int grow = g * HH + cta * 8 + j;
        float4 v = ((const float4*)(Whh + (size_t)grow * HH))[k4];
        ((float4*)(sW + r * HH))[k4] = v;
    }
    const float bhr0 = bhh[c0],          bhr1 = bhh[c1];
    const float bhz0 = bhh[HH + c0],     bhz1 = bhh[HH + c1];
    const float bhn0 = bhh[2 * HH + c0], bhn1 = bhh[2 * HH + c1];
    __syncthreads();

    const float* wr0 = sW + ((j0 + 0) * 3 + 0) * HH;
    const float* wr1 = sW + ((j0 + 1) * 3 + 0) * HH;
    const float* wz0 = sW + ((j0 + 0) * 3 + 1) * HH;
    const float* wz1 = sW + ((j0 + 1) * 3 + 1) * HH;
    const float* wn0 = sW + ((j0 + 0) * 3 + 2) * HH;
    const float* wn1 = sW + ((j0 + 1) * 3 + 2) * HH;

    const int b  = lane & 7;
    const int ks = lane >> 3;
    const float* hrow = sh + b * SHSTR;

    // Barrier base (flags all equal at kernel entry; monotonic protocol)
    const unsigned v0 = ld_acquire_gpu(&g_flags[cta * FPAD]);

    // Prefetch step-0 gate values
    float xv[6];
    if (lane < 8) {
        const float* p = g_xproj + (size_t)lane * G3;   // t = 0
        xv[0] = __ldcs(p + c0);           xv[1] = __ldcs(p + c1);
        xv[2] = __ldcs(p + HH + c0);      xv[3] = __ldcs(p + HH + c1);
        xv[4] = __ldcs(p + 2 * HH + c0);  xv[5] = __ldcs(p + 2 * HH + c1);
    }

    for (int t = 0; t < TT; ++t) {
        // ---- stage h into SMEM (t=0: zeros; else L2-coherent read) ----
        if (t == 0) {
            float4 z4 = make_float4(0.f, 0.f, 0.f, 0.f);
            for (int idx = tid; idx < (BB * SHSTR) / 4; idx += NTHR)
                ((float4*)sh)[idx] = z4;
        } else {
            const float* hin = g_h[t & 1];
#pragma unroll
            for (int i = 0; i < 16; ++i) {
                int lin = tid + i * NTHR;       // 0..2047 float4
                int bb  = lin >> 8;             // 256 float4 per batch
                int k4  = lin & 255;
                ((float4*)(sh + bb * SHSTR))[k4] =
                    __ldcg(((const float4*)(hin + (size_t)bb * HH)) + k4);
            }
        }

        // Prefetch NEXT step's gate values (overlaps compute; read-only data)
        float xnx[6] = {0.f, 0.f, 0.f, 0.f, 0.f, 0.f};
        if (lane < 8 && t + 1 < TT) {
            const float* p = g_xproj + ((size_t)(t + 1) * BB + lane) * G3;
            xnx[0] = __ldcs(p + c0);           xnx[1] = __ldcs(p + c1);
            xnx[2] = __ldcs(p + HH + c0);      xnx[3] = __ldcs(p + HH + c1);
            xnx[4] = __ldcs(p + 2 * HH + c0);  xnx[5] = __ldcs(p + 2 * HH + c1);
        }
        __syncthreads();

        // ---- dot products: 6 accs (gate x col) for this lane's batch ----
        u64 ar0 = 0ull, ar1 = 0ull, az0 = 0ull, az1 = 0ull, an0 = 0ull, an1 = 0ull;
        const int kbase = ks * 2;
#pragma unroll 4
        for (int j = 0; j < 128; ++j) {
            int kf = j * 8 + kbase;            // float offset of this lane's k-pair
            u64 h2 = *(const u64*)(hrow + kf);
            ar0 = fma2(*(const u64*)(wr0 + kf), h2, ar0);
            ar1 = fma2(*(const u64*)(wr1 + kf), h2, ar1);
            az0 = fma2(*(const u64*)(wz0 + kf), h2, az0);
            az1 = fma2(*(const u64*)(wz1 + kf), h2, az1);
            an0 = fma2(*(const u64*)(wn0 + kf), h2, an0);
            an1 = fma2(*(const u64*)(wn1 + kf), h2, an1);
        }

        // fold halves, reduce across the 4 ks-groups (lanes b, b+8, b+16, b+24)
        float s0 = fold2(ar0), s1 = fold2(ar1), s2 = fold2(az0);
        float s3 = fold2(az1), s4 = fold2(an0), s5 = fold2(an1);
#pragma unroll
        for (int off = 8; off <= 16; off <<= 1) {
            s0 += __shfl_xor_sync(0xffffffffu, s0, off);
            s1 += __shfl_xor_sync(0xffffffffu, s1, off);
            s2 += __shfl_xor_sync(0xffffffffu, s2, off);
            s3 += __shfl_xor_sync(0xffffffffu, s3, off);
            s4 += __shfl_xor_sync(0xffffffffu, s4, off);
            s5 += __shfl_xor_sync(0xffffffffu, s5, off);
        }

        // ---- lanes 0..7 finalize their batch for both cols ----
        // b_hh_n sits INSIDE the r* term: n = tanh(xn + r*(Whh_n.h + bhh_n))
        if (lane < 8) {
            float hp0 = hrow[c0];
            float hp1 = hrow[c1];
            float r0 = sigmoidf_(xv[0] + bhr0 + s0);
            float r1 = sigmoidf_(xv[1] + bhr1 + s1);
            float z0 = sigmoidf_(xv[2] + bhz0 + s2);
            float z1 = sigmoidf_(xv[3] + bhz1 + s3);
            float n0 = tanhf(xv[4] + r0 * (s4 + bhn0));
            float n1 = tanhf(xv[5] + r1 * (s5 + bhn1));
            float h0 = (1.0f - z0) * n0 + z0 * hp0;
            float h1 = (1.0f - z1) * n1 + z1 * hp1;
            float* orow = out + ((size_t)b * TT + t) * HH;
            orow[c0] = h0;
            orow[c1] = h1;
            float* hnext = g_h[(t + 1) & 1] + (size_t)b * HH;
            __stcg(hnext + c0, h0);
            __stcg(hnext + c1, h1);
        }

        // ---- distributed single-phase grid barrier (release/acquire) ----
        __syncthreads();
        if (tid == 0) st_release_gpu(&g_flags[cta * FPAD], v0 + (unsigned)(t + 1));
        while (ld_acquire_gpu(&g_flags[tid * FPAD]) - v0 < (unsigned)(t + 1)) { }
        __syncthreads();

#pragma unroll
        for (int i = 0; i < 6; ++i) xv[i] = xnx[i];
    }
    // flags end equal at v0 + TT for all CTAs -> valid base for next replay
}

// ---------------- launcher ---------------------------------------------------
extern "C" void kernel_launch(void* const* d_in, const int* in_sizes, int n_in,
                              void* d_out, int out_size) {
    const float* x   = (const float*)d_in[0];
    const float* Wih = (const float*)d_in[1];
    const float* bih = (const float*)d_in[2];
    const float* Whh = (const float*)d_in[3];
    const float* bhh = (const float*)d_in[4];
    float* out = (float*)d_out;

    (void)in_sizes; (void)n_in; (void)out_size;

    const int kSmem = (24 * HH + BB * SHSTR) * (int)sizeof(float);  // ~128.2 KB
    cudaFuncSetAttribute(gru_recurrent_kernel,
                         cudaFuncAttributeMaxDynamicSharedMemorySize, kSmem);

    dim3 g1(G3 / BN, (BB * TT) / BM);   // 24 x 256
    xproj_gemm_kernel<<<g1, 256>>>(x, Wih, bih);

    gru_recurrent_kernel<<<NCTA, NTHR, kSmem>>>(Whh, bhh, out);
}

// round 6
// speedup vs baseline: 1.7496x; 1.7496x over previous
#include <cuda_runtime.h>
#include <math.h>

#define BB 8
#define TT 2048
#define HH 1024
#define G3 3072
#define NCTA 128
#define NTHR 256
#define FPAD 32      // one flag per 128B line
#define SHSTR 1032   // padded h row stride (floats)

typedef unsigned long long u64;

// ---------------- persistent scratch (device globals; zero-initialized) -----
__device__ float g_xproj[(size_t)TT * BB * G3];   // [t][b][3H]
__device__ float g_h[2][BB * HH];                 // double-buffered hidden state
__device__ unsigned int g_flags[NCTA * FPAD];     // grid-barrier flags (monotonic)

__device__ __forceinline__ void st_release_gpu(unsigned int* p, unsigned int v) {
    asm volatile("st.release.gpu.u32 [%0], %1;" :: "l"(p), "r"(v) : "memory");
}
__device__ __forceinline__ unsigned int ld_acquire_gpu(const unsigned int* p) {
    unsigned int v;
    asm volatile("ld.acquire.gpu.u32 %0, [%1];" : "=r"(v) : "l"(p) : "memory");
    return v;
}
// packed fp32x2 FMA (Blackwell)
__device__ __forceinline__ u64 fma2(u64 a, u64 b, u64 c) {
    u64 d;
    asm("fma.rn.f32x2 %0, %1, %2, %3;" : "=l"(d) : "l"(a), "l"(b), "l"(c));
    return d;
}
__device__ __forceinline__ float fold2(u64 v) {
    return __uint_as_float((unsigned)v) + __uint_as_float((unsigned)(v >> 32));
}
__device__ __forceinline__ float sigmoidf_(float v) {
    return 1.0f / (1.0f + expf(-v));
}

// ---------------- kernel A: x_proj = x @ W_ih^T + b_ih ----------------------
// (R4 version: conflict-free Bs column map tx+16u; epilogue scatters [t][b][3H])
#define BM 64
#define BN 128
#define BKK 16
#define APAD 18
#define BPAD 18

__global__ void __launch_bounds__(256, 2) xproj_gemm_kernel(
    const float* __restrict__ x,     // [b][t][h]
    const float* __restrict__ Wih,   // [3H, H]
    const float* __restrict__ bih)   // [3H]
{
    __shared__ float As[BM * APAD];
    __shared__ float Bs[BN * BPAD];

    const int tid = threadIdx.x;
    const int m0 = blockIdx.y * BM;
    const int n0 = blockIdx.x * BN;
    const int tx = tid & 15;
    const int ty = tid >> 4;

    const int ldRow = tid >> 2;
    const int ldCol = (tid & 3) * 4;

    const float* aPtr  = x   + (size_t)(m0 + ldRow) * HH + ldCol;
    const float* bPtr0 = Wih + (size_t)(n0 + ldRow) * HH + ldCol;
    const float* bPtr1 = Wih + (size_t)(n0 + ldRow + 64) * HH + ldCol;

    u64 acc[4][8];
#pragma unroll
    for (int i = 0; i < 4; ++i)
#pragma unroll
        for (int u = 0; u < 8; ++u) acc[i][u] = 0ull;

    for (int k0 = 0; k0 < HH; k0 += BKK) {
        float4 av  = *(const float4*)(aPtr  + k0);
        float4 bv0 = *(const float4*)(bPtr0 + k0);
        float4 bv1 = *(const float4*)(bPtr1 + k0);

        *(float2*)&As[ldRow * APAD + ldCol + 0] = make_float2(av.x, av.y);
        *(float2*)&As[ldRow * APAD + ldCol + 2] = make_float2(av.z, av.w);
        *(float2*)&Bs[ldRow * BPAD + ldCol + 0] = make_float2(bv0.x, bv0.y);
        *(float2*)&Bs[ldRow * BPAD + ldCol + 2] = make_float2(bv0.z, bv0.w);
        *(float2*)&Bs[(ldRow + 64) * BPAD + ldCol + 0] = make_float2(bv1.x, bv1.y);
        *(float2*)&Bs[(ldRow + 64) * BPAD + ldCol + 2] = make_float2(bv1.z, bv1.w);
        __syncthreads();

#pragma unroll
        for (int kk2 = 0; kk2 < BKK / 2; ++kk2) {
            u64 a2[4];
#pragma unroll
            for (int i = 0; i < 4; ++i)
                a2[i] = *(const u64*)&As[(ty * 4 + i) * APAD + kk2 * 2];
            u64 b2[8];
#pragma unroll
            for (int u = 0; u < 8; ++u)
                b2[u] = *(const u64*)&Bs[(tx + 16 * u) * BPAD + kk2 * 2];
#pragma unroll
            for (int i = 0; i < 4; ++i)
#pragma unroll
                for (int u = 0; u < 8; ++u)
                    acc[i][u] = fma2(a2[i], b2[u], acc[i][u]);
        }
        __syncthreads();
    }

#pragma unroll
    for (int i = 0; i < 4; ++i) {
        int m = m0 + ty * 4 + i;
        int b = m >> 11;
        int t = m & 2047;
        float* orow = g_xproj + ((size_t)t * BB + b) * G3 + n0;
#pragma unroll
        for (int u = 0; u < 8; ++u) {
            int c = tx + 16 * u;
            orow[c] = fold2(acc[i][u]) + __ldg(bih + n0 + c);
        }
    }
}

// ---------------- kernel B: persistent recurrence ---------------------------
// 256 threads = 8 warps. warp -> (p = wid&3, kh = wid>>2): col-pair {2p,2p+1},
// K-half kh. lane -> (b = lane&7, ks = lane>>3). W packed in smem as
// sWp[p][kp][row0..5] so 6 W values per k-pair = 3 broadcast LDS.128.
// Partial sums combined across kh via small smem staging.
__global__ void __launch_bounds__(NTHR, 1) gru_recurrent_kernel(
    const float* __restrict__ Whh,   // [3H, H]
    const float* __restrict__ bhh,   // [3H]
    float* __restrict__ out)         // [B, T, H]
{
    extern __shared__ float smem[];
    u64*   sWp  = (u64*)smem;                    // [4][512][6] u64 = 96KB
    float* sh   = smem + (4 * 512 * 6) * 2;      // [8][SHSTR]  ~33KB
    float* sRed = sh + BB * SHSTR;               // [8 warps][8 b][8] = 2KB

    const int tid  = threadIdx.x;
    const int cta  = blockIdx.x;
    const int wid  = tid >> 5;
    const int lane = tid & 31;
    const int p    = wid & 3;
    const int kh   = wid >> 2;
    const int b    = lane & 7;
    const int ks   = lane >> 3;

    // ---- pack W_hh into sWp: sWp[((p*512 + kp)*6 + jloc*3 + g)] = Whh pair ----
    // rows for p: cols {cta*8+2p, cta*8+2p+1} x gates {0,1,2}; kp = k-pair index
    for (int idx = tid; idx < 24 * 512; idx += NTHR) {
        int row = idx >> 9;          // 0..23  (jglob*3 + g ordering below)
        int kp  = idx & 511;
        int jglob = row / 3;         // 0..7 local col
        int g     = row % 3;
        int pp    = jglob >> 1;
        int jloc  = jglob & 1;
        const float* src = Whh + (size_t)(g * HH + cta * 8 + jglob) * HH + kp * 2;
        u64 v = *(const u64*)src;
        sWp[((pp * 512 + kp) * 6) + jloc * 3 + g] = v;
    }
    __syncthreads();

    const int c0 = cta * 8 + 2 * p;   // this warp's first col
    // per-finalize-lane biases (warps kh==0, lanes<8 use them)
    float bh[6];
#pragma unroll
    for (int jl = 0; jl < 2; ++jl)
#pragma unroll
        for (int g = 0; g < 3; ++g)
            bh[jl * 3 + g] = bhh[g * HH + c0 + jl];

    const u64* wbase = sWp + (size_t)p * 512 * 6;
    const float* hrow = sh + b * SHSTR;

    // barrier base (monotonic flags)
    const unsigned v0 = ld_acquire_gpu(&g_flags[cta * FPAD]);

    // step-0 xproj prefetch (warps kh==0, lanes<8; b = lane)
    float xv[6];
    if (kh == 0 && lane < 8) {
        const float* px = g_xproj + (size_t)b * G3;   // t=0
#pragma unroll
        for (int g = 0; g < 3; ++g) {
            float2 v = *(const float2*)(px + g * HH + c0);
            xv[0 * 3 + g] = v.x;   // jloc=0
            xv[1 * 3 + g] = v.y;   // jloc=1
        }
    }

    for (int t = 0; t < TT; ++t) {
        // ---- stage h(t) into smem ----
        if (t == 0) {
            float4 z4 = make_float4(0.f, 0.f, 0.f, 0.f);
            for (int i = tid; i < (BB * SHSTR) / 4; i += NTHR)
                ((float4*)sh)[i] = z4;
        } else {
            const float* hin = g_h[t & 1];
#pragma unroll
            for (int i = 0; i < 8; ++i) {
                int lin = tid + i * NTHR;       // 0..2047 float4
                int bb  = lin >> 8;
                int k4  = lin & 255;
                ((float4*)(sh + bb * SHSTR))[k4] =
                    __ldcg(((const float4*)(hin + (size_t)bb * HH)) + k4);
            }
        }

        // prefetch next step's xproj during compute
        float xnx[6] = {0.f, 0.f, 0.f, 0.f, 0.f, 0.f};
        if (kh == 0 && lane < 8 && t + 1 < TT) {
            const float* px = g_xproj + ((size_t)(t + 1) * BB + b) * G3;
#pragma unroll
            for (int g = 0; g < 3; ++g) {
                float2 v = *(const float2*)(px + g * HH + c0);
                xnx[0 * 3 + g] = v.x;
                xnx[1 * 3 + g] = v.y;
            }
        }
        __syncthreads();

        // ---- partial dot products over this warp's K-half ----
        u64 acc0 = 0ull, acc1 = 0ull, acc2 = 0ull;
        u64 acc3 = 0ull, acc4 = 0ull, acc5 = 0ull;
        const int kp0 = kh * 256 + ks;          // k-pair start
#pragma unroll 8
        for (int j = 0; j < 64; ++j) {
            int kp = kp0 + j * 4;
            const u64* wp = wbase + (size_t)kp * 6;
            ulonglong2 wA = *(const ulonglong2*)(wp + 0);  // rows 0,1
            ulonglong2 wB = *(const ulonglong2*)(wp + 2);  // rows 2,3
            ulonglong2 wC = *(const ulonglong2*)(wp + 4);  // rows 4,5
            u64 h2 = *(const u64*)(hrow + 2 * kp);
            acc0 = fma2(wA.x, h2, acc0);
            acc1 = fma2(wA.y, h2, acc1);
            acc2 = fma2(wB.x, h2, acc2);
            acc3 = fma2(wB.y, h2, acc3);
            acc4 = fma2(wC.x, h2, acc4);
            acc5 = fma2(wC.y, h2, acc5);
        }

        // fold + reduce over ks (lanes b, b+8, b+16, b+24)
        float s0 = fold2(acc0), s1 = fold2(acc1), s2 = fold2(acc2);
        float s3 = fold2(acc3), s4 = fold2(acc4), s5 = fold2(acc5);
#pragma unroll
        for (int off = 8; off <= 16; off <<= 1) {
            s0 += __shfl_xor_sync(0xffffffffu, s0, off);
            s1 += __shfl_xor_sync(0xffffffffu, s1, off);
            s2 += __shfl_xor_sync(0xffffffffu, s2, off);
            s3 += __shfl_xor_sync(0xffffffffu, s3, off);
            s4 += __shfl_xor_sync(0xffffffffu, s4, off);
            s5 += __shfl_xor_sync(0xffffffffu, s5, off);
        }

        // stage partials (lanes 0..7 of every warp)
        if (lane < 8) {
            float* dst = sRed + ((wid * 8 + b) * 8);
            dst[0] = s0; dst[1] = s1; dst[2] = s2;
            dst[3] = s3; dst[4] = s4; dst[5] = s5;
        }
        __syncthreads();

        // ---- combine K-halves + activations (warps kh==0, lanes<8) ----
        if (kh == 0 && lane < 8) {
            const float* r0 = sRed + ((p * 8 + b) * 8);          // kh=0 partial
            const float* r1 = sRed + (((4 + p) * 8 + b) * 8);    // kh=1 partial
            float gsum[6];
#pragma unroll
            for (int i = 0; i < 6; ++i) gsum[i] = r0[i] + r1[i];

            float2 hp = *(const float2*)(hrow + c0);   // prev h, cols c0,c0+1
            // row order: jloc*3 + g, g: 0=r,1=z,2=n. bhh_n INSIDE r* term.
            float rr0 = sigmoidf_(xv[0] + bh[0] + gsum[0]);
            float zz0 = sigmoidf_(xv[1] + bh[1] + gsum[1]);
            float nn0 = tanhf(xv[2] + rr0 * (gsum[2] + bh[2]));
            float rr1 = sigmoidf_(xv[3] + bh[3] + gsum[3]);
            float zz1 = sigmoidf_(xv[4] + bh[4] + gsum[4]);
            float nn1 = tanhf(xv[5] + rr1 * (gsum[5] + bh[5]));
            float h0 = (1.0f - zz0) * nn0 + zz0 * hp.x;
            float h1 = (1.0f - zz1) * nn1 + zz1 * hp.y;

            float2 o2 = make_float2(h0, h1);
            *(float2*)(out + ((size_t)b * TT + t) * HH + c0) = o2;
            float* hnext = g_h[(t + 1) & 1] + (size_t)b * HH + c0;
            asm volatile("st.global.cg.v2.f32 [%0], {%1, %2};"
                         :: "l"(hnext), "f"(h0), "f"(h1) : "memory");
        }

        // ---- grid barrier (release/acquire, distributed flags) ----
        __syncthreads();
        if (tid == 0) st_release_gpu(&g_flags[cta * FPAD], v0 + (unsigned)(t + 1));
        if (tid < NCTA) {
            while (ld_acquire_gpu(&g_flags[tid * FPAD]) - v0 < (unsigned)(t + 1)) { }
        }
        __syncthreads();

#pragma unroll
        for (int i = 0; i < 6; ++i) xv[i] = xnx[i];
    }
}

// ---------------- launcher ---------------------------------------------------
extern "C" void kernel_launch(void* const* d_in, const int* in_sizes, int n_in,
                              void* d_out, int out_size) {
    const float* x   = (const float*)d_in[0];
    const float* Wih = (const float*)d_in[1];
    const float* bih = (const float*)d_in[2];
    const float* Whh = (const float*)d_in[3];
    const float* bhh = (const float*)d_in[4];
    float* out = (float*)d_out;

    (void)in_sizes; (void)n_in; (void)out_size;

    // smem: W pack 96KB + h stage ~33KB + reduce 2KB
    const int kSmem = (4 * 512 * 6) * 8 + (BB * SHSTR) * 4 + (8 * 8 * 8) * 4;
    cudaFuncSetAttribute(gru_recurrent_kernel,
                         cudaFuncAttributeMaxDynamicSharedMemorySize, kSmem);

    dim3 g1(G3 / BN, (BB * TT) / BM);   // 24 x 256
    xproj_gemm_kernel<<<g1, 256>>>(x, Wih, bih);

    gru_recurrent_kernel<<<NCTA, NTHR, kSmem>>>(Whh, bhh, out);
}